// round 2
// baseline (speedup 1.0000x reference)
#include <cuda_runtime.h>
#include <cuda_bf16.h>
#include <cstdint>

// Problem constants (fixed by the dataset)
#define B_DIM 32
#define L_DIM 256
#define H_DIM 512
#define H4    (H_DIM / 4)      // 128 float4 per row
#define T_MAX (L_DIM * 15)     // 3840: max possible total duration

// Scratch: frame -> encoder index map (-1 = beyond total, masked/zero)
__device__ int g_idx[B_DIM * T_MAX];

// ---------------------------------------------------------------------------
// Kernel 1: per-batch cumsum of durations, scatter frame->index map, fill
// tail with -1, and write the mask floats directly into d_out's mask region.
// One block per batch, 256 threads (== L).
// ---------------------------------------------------------------------------
__global__ void k_prep(const int* __restrict__ dur,
                       float* __restrict__ mask_out,   // points at d_out + B*T*H
                       int T) {
    const int b = blockIdx.x;
    const int i = threadIdx.x;          // 0..255 == encoder position
    __shared__ int s_warp[8];

    int d = dur[b * L_DIM + i];

    // Warp-level inclusive scan
    int v = d;
    const int lane = i & 31;
    const int wid  = i >> 5;
    #pragma unroll
    for (int off = 1; off < 32; off <<= 1) {
        int n = __shfl_up_sync(0xffffffffu, v, off);
        if (lane >= off) v += n;
    }
    if (lane == 31) s_warp[wid] = v;
    __syncthreads();

    // Scan the 8 warp sums in warp 0
    if (wid == 0) {
        int w = (lane < 8) ? s_warp[lane] : 0;
        #pragma unroll
        for (int off = 1; off < 8; off <<= 1) {
            int n = __shfl_up_sync(0xffffffffu, w, off);
            if (lane >= off) w += n;
        }
        if (lane < 8) s_warp[lane] = w;
    }
    __syncthreads();

    const int incl  = v + ((wid > 0) ? s_warp[wid - 1] : 0); // inclusive csum
    const int total = s_warp[7];                             // sum of all durations
    const int start = incl - d;                              // exclusive csum

    int* gi = g_idx + b * T;

    // Scatter: frames [start, start+d) map to encoder position i
    for (int k = 0; k < d; ++k)
        gi[start + k] = i;

    // Tail: frames beyond total are masked
    for (int t = total + i; t < T; t += L_DIM)
        gi[t] = -1;

    // Mask output (float 1.0/0.0 matches int32 reference numerically)
    float* mrow = mask_out + (size_t)b * T;
    for (int t = i; t < T; t += L_DIM)
        mrow[t] = (t < total) ? 1.0f : 0.0f;
}

// ---------------------------------------------------------------------------
// Kernel 2: gather rows. One block per output frame (b,t); 128 threads each
// move one float4 (16B) of the 2KB row. Zero-fill masked frames (overwrites
// the harness's 0xAA poison).
// ---------------------------------------------------------------------------
__global__ void __launch_bounds__(H4, 8)
k_expand(const float4* __restrict__ x4,
         float4* __restrict__ out4,
         int T) {
    const int bt = blockIdx.x;         // b*T + t
    const int b  = bt / T;
    const int idx = g_idx[bt];

    float4 v;
    if (idx >= 0) {
        v = __ldg(&x4[(size_t)(b * L_DIM + idx) * H4 + threadIdx.x]);
    } else {
        v = make_float4(0.f, 0.f, 0.f, 0.f);
    }
    out4[(size_t)bt * H4 + threadIdx.x] = v;
}

// ---------------------------------------------------------------------------
extern "C" void kernel_launch(void* const* d_in, const int* in_sizes, int n_in,
                              void* d_out, int out_size) {
    const float* x   = (const float*)d_in[0];   // (B, L, H) float32
    const int*   dur = (const int*)d_in[1];     // (B, L)    int32

    // out_size = B*T*H + B*T = B*T*(H+1)  =>  T
    const int T = out_size / (B_DIM * (H_DIM + 1));

    float* out      = (float*)d_out;                      // (B, T, H)
    float* mask_out = out + (size_t)B_DIM * T * H_DIM;    // (B, T)

    k_prep<<<B_DIM, L_DIM>>>(dur, mask_out, T);
    k_expand<<<B_DIM * T, H4>>>((const float4*)x, (float4*)out, T);

    (void)in_sizes; (void)n_in;
}

// round 3
// speedup vs baseline: 1.5127x; 1.5127x over previous
#include <cuda_runtime.h>
#include <cuda_bf16.h>
#include <cstdint>

// Problem constants (fixed by the dataset)
#define B_DIM 32
#define L_DIM 256
#define H_DIM 512
#define H4    (H_DIM / 4)      // 128 float4 per row
#define T_MAX (L_DIM * 15)     // 3840: max possible total duration
#define FPB   8                // frames per expand block

// Scratch: frame -> SOURCE ROW index (b*L + idx), or -1 when masked (zero-fill)
__device__ int g_row[B_DIM * T_MAX];

// ---------------------------------------------------------------------------
// Kernel 1: per-batch cumsum of durations, scatter frame->source-row map,
// fill tail with -1, write mask floats directly into d_out's mask region.
// One block per batch, 256 threads (== L).
// ---------------------------------------------------------------------------
__global__ void k_prep(const int* __restrict__ dur,
                       float* __restrict__ mask_out,   // d_out + B*T*H
                       int T) {
    const int b = blockIdx.x;
    const int i = threadIdx.x;          // encoder position 0..255
    __shared__ int s_warp[8];

    int d = dur[b * L_DIM + i];

    // Warp inclusive scan
    int v = d;
    const int lane = i & 31;
    const int wid  = i >> 5;
    #pragma unroll
    for (int off = 1; off < 32; off <<= 1) {
        int n = __shfl_up_sync(0xffffffffu, v, off);
        if (lane >= off) v += n;
    }
    if (lane == 31) s_warp[wid] = v;
    __syncthreads();
    if (wid == 0) {
        int w = (lane < 8) ? s_warp[lane] : 0;
        #pragma unroll
        for (int off = 1; off < 8; off <<= 1) {
            int n = __shfl_up_sync(0xffffffffu, w, off);
            if (lane >= off) w += n;
        }
        if (lane < 8) s_warp[lane] = w;
    }
    __syncthreads();

    const int incl  = v + ((wid > 0) ? s_warp[wid - 1] : 0);
    const int total = s_warp[7];
    const int start = incl - d;

    int* gr = g_row + b * T;
    const int srcrow = b * L_DIM + i;   // precomputed source row for expand

    for (int k = 0; k < d; ++k)
        gr[start + k] = srcrow;

    for (int t = total + i; t < T; t += L_DIM)
        gr[t] = -1;

    float* mrow = mask_out + (size_t)b * T;
    for (int t = i; t < T; t += L_DIM)
        mrow[t] = (t < total) ? 1.0f : 0.0f;
}

// ---------------------------------------------------------------------------
// Kernel 2: gather/expand rows with MLP=4 per thread.
// 256 threads per block, FPB=8 frames per block:
//   col  = tid & 127        (float4 column within the 512-float row)
//   fsub = tid >> 7  (0..1) — two frame lanes
//   each thread covers frames fsub, fsub+2, fsub+4, fsub+6 of the block.
// 4 independent LDG.128 then 4 STG.128 -> latency hidden by MLP.
// ---------------------------------------------------------------------------
__global__ void __launch_bounds__(256, 4)
k_expand(const float4* __restrict__ x4,
         float4* __restrict__ out4,
         int nbt) {
    const int tid  = threadIdx.x;
    const int c    = tid & (H4 - 1);
    const int fsub = tid >> 7;                 // 0 or 1
    const int bt0  = blockIdx.x * FPB + fsub;

    int rows[4];
    #pragma unroll
    for (int k = 0; k < 4; ++k) {
        const int f = bt0 + 2 * k;
        rows[k] = (f < nbt) ? __ldg(&g_row[f]) : -2;   // -2: out of range, skip store
    }

    float4 vals[4];
    #pragma unroll
    for (int k = 0; k < 4; ++k) {
        if (rows[k] >= 0)
            vals[k] = __ldg(&x4[(size_t)rows[k] * H4 + c]);
        else
            vals[k] = make_float4(0.f, 0.f, 0.f, 0.f);
    }

    #pragma unroll
    for (int k = 0; k < 4; ++k) {
        const int f = bt0 + 2 * k;
        if (rows[k] != -2)
            out4[(size_t)f * H4 + c] = vals[k];
    }
}

// ---------------------------------------------------------------------------
extern "C" void kernel_launch(void* const* d_in, const int* in_sizes, int n_in,
                              void* d_out, int out_size) {
    const float* x   = (const float*)d_in[0];   // (B, L, H) float32
    const int*   dur = (const int*)d_in[1];     // (B, L)    int32

    // out_size = B*T*(H+1)  =>  T
    const int T   = out_size / (B_DIM * (H_DIM + 1));
    const int nbt = B_DIM * T;

    float* out      = (float*)d_out;                      // (B, T, H)
    float* mask_out = out + (size_t)nbt * H_DIM;          // (B, T)

    k_prep<<<B_DIM, L_DIM>>>(dur, mask_out, T);
    k_expand<<<(nbt + FPB - 1) / FPB, 256>>>((const float4*)x, (float4*)out, nbt);

    (void)in_sizes; (void)n_in;
}